// round 3
// baseline (speedup 1.0000x reference)
#include <cuda_runtime.h>

// ---------------- problem constants ----------------
#define NN   24          // real nodes
#define NP1  25          // + virtual node
#define BB   4
#define CC   8
#define HH   96
#define WW   96
#define KK   4
#define EE   96
#define HW          (HH*WW)            // 9216
#define NODE_ELEMS  (BB*CC*HW)         // 294912
#define ACT_ELEMS   (NP1*NODE_ELEMS)   // 7372800
#define FUT_ELEMS   (NN*NODE_ELEMS)    // 7077888
#define INIT_PLAST  0.1f

// ---------------- device scratch (no allocs allowed) ----------------
__device__ float g_act[ACT_ELEMS];        // sigmoid(states), ~29.5 MB
__device__ int   g_off[NN + 1];           // CSR offsets by dst node
__device__ int   g_edge_id[EE];           // edge index (for weights)
__device__ int   g_edge_src[EE];          // src node of edge
__device__ float g_edge_scale[EE];        // plasticity[e] / deg[dst[e]]
__device__ float g_part[NN * 8];          // per-node partial sums of sigmoid(future)

__device__ __forceinline__ float sigmoidf_(float x) {
    return 1.0f / (1.0f + __expf(-x));
}

// ---------------- kernel 1: act = sigmoid(states) ----------------
__global__ void k_sigmoid(const float* __restrict__ st) {
    int n4 = ACT_ELEMS / 4;
    const float4* s4 = (const float4*)st;
    float4* a4 = (float4*)g_act;
    for (int i = blockIdx.x * blockDim.x + threadIdx.x; i < n4;
         i += gridDim.x * blockDim.x) {
        float4 v = s4[i];
        v.x = sigmoidf_(v.x);
        v.y = sigmoidf_(v.y);
        v.z = sigmoidf_(v.z);
        v.w = sigmoidf_(v.w);
        a4[i] = v;
    }
}

// ---------------- kernel 2: build dst-CSR + fused scale (deterministic) --------
__global__ void k_meta(const int* __restrict__ src, const int* __restrict__ dst,
                       const float* __restrict__ plast) {
    __shared__ int ssrc[EE];
    __shared__ int sdst[EE];
    __shared__ float spl[EE];
    int tid = threadIdx.x;
    if (tid < EE) {
        ssrc[tid] = src[tid];
        sdst[tid] = dst[tid];
        spl[tid]  = plast[tid];
    }
    __syncthreads();
    if (tid == 0) {
        int cnt[NN];
        for (int n = 0; n < NN; n++) cnt[n] = 0;
        for (int e = 0; e < EE; e++) cnt[sdst[e]]++;
        int off = 0;
        int cur[NN];
        float inv[NN];
        for (int n = 0; n < NN; n++) {
            g_off[n] = off;
            cur[n] = off;
            int c = cnt[n] > 0 ? cnt[n] : 1;
            inv[n] = 1.0f / (float)c;
            off += cnt[n];
        }
        g_off[NN] = off;
        for (int e = 0; e < EE; e++) {          // stable order -> deterministic
            int d = sdst[e];
            int slot = cur[d]++;
            g_edge_id[slot]    = e;
            g_edge_src[slot]   = ssrc[e];
            g_edge_scale[slot] = spl[e] * inv[d];
        }
    }
}

// ---------------- kernel 3: conv + mean-aggregate into future -----------------
// Tile: 32x32 output pixels per (node,b). 256 threads: 32 rows x 8 threads,
// each thread computes 4 consecutive x-pixels for all 8 Cout (32 accumulators).
// FFMA-issue-bound by design: vectorized LDS.128 for input window and weights.
__global__ void __launch_bounds__(256) k_conv(const float* __restrict__ weights,
                                              float* __restrict__ out) {
    __shared__ __align__(16) float sin_[35 * 36];  // 35x35 halo tile, stride 36
    __shared__ __align__(16) float ws[8 * 16];     // weights[co][ky*4+kx] * scale

    const int node = blockIdx.z;
    const int b    = blockIdx.y;
    const int ty0  = (blockIdx.x / 3) * 32;
    const int tx0  = (blockIdx.x % 3) * 32;
    const int tid  = threadIdx.x;
    const int ty   = tid >> 3;
    const int txq  = (tid & 7) << 2;

    // precompute tile-load addresses once (hoisted out of the ci loop)
    int lof[5], gof[5];
#pragma unroll
    for (int j = 0; j < 5; j++) {
        int i = tid + j * 256;
        lof[j] = -1;
        gof[j] = -1;
        if (i < 35 * 35) {
            int r = i / 35, c = i - r * 35;
            lof[j] = r * 36 + c;
            int gy = ty0 - 1 + r, gx = tx0 - 1 + c;
            if ((unsigned)gy < (unsigned)HH && (unsigned)gx < (unsigned)WW)
                gof[j] = gy * WW + gx;
        }
    }
    const int widx = (tid >> 4) * (CC * KK * KK) + (tid & 15);  // for tid<128

    float acc[8][4];
#pragma unroll
    for (int co = 0; co < 8; co++)
#pragma unroll
        for (int p = 0; p < 4; p++) acc[co][p] = 0.0f;

    const int s0 = __ldg(&g_off[node]), s1 = __ldg(&g_off[node + 1]);
    for (int s = s0; s < s1; ++s) {
        const int   e  = __ldg(&g_edge_id[s]);
        const int   sn = __ldg(&g_edge_src[s]);
        const float sc = __ldg(&g_edge_scale[s]);
        const float* abase = g_act + ((size_t)(sn * BB + b)) * (CC * HW);
        const float* wbase = weights + (size_t)e * (CC * CC * KK * KK);

#pragma unroll 1
        for (int ci = 0; ci < CC; ci++) {
            __syncthreads();
            const float* a = abase + ci * HW;
#pragma unroll
            for (int j = 0; j < 5; j++) {
                if (lof[j] >= 0)
                    sin_[lof[j]] = (gof[j] >= 0) ? __ldg(&a[gof[j]]) : 0.0f;
            }
            if (tid < 128) ws[tid] = __ldg(&wbase[widx + ci * (KK * KK)]) * sc;
            __syncthreads();

#pragma unroll
            for (int ky = 0; ky < 4; ky++) {
                const float* rp = &sin_[(ty + ky) * 36 + txq];
                float4 va = *(const float4*)rp;
                float4 vb = *(const float4*)(rp + 4);
#pragma unroll
                for (int co = 0; co < 8; co++) {
                    float4 wv = *(const float4*)&ws[co * 16 + ky * 4];
                    acc[co][0] += wv.x * va.x + wv.y * va.y + wv.z * va.z + wv.w * va.w;
                    acc[co][1] += wv.x * va.y + wv.y * va.z + wv.z * va.w + wv.w * vb.x;
                    acc[co][2] += wv.x * va.z + wv.y * va.w + wv.z * vb.x + wv.w * vb.y;
                    acc[co][3] += wv.x * va.w + wv.y * vb.x + wv.z * vb.y + wv.w * vb.z;
                }
            }
        }
    }

    const int y = ty0 + ty, x = tx0 + txq;
    float* ob = out + ((size_t)(node * BB + b)) * (CC * HW) + y * WW + x;
#pragma unroll
    for (int co = 0; co < 8; co++) {
        float4 v = make_float4(acc[co][0], acc[co][1], acc[co][2], acc[co][3]);
        *(float4*)(ob + co * HW) = v;
    }
}

// ---------------- kernel 4: per-node partial sums of sigmoid(future) ----------
// 24 nodes x 8 chunks = 192 blocks, deterministic tree reduction per block.
__global__ void __launch_bounds__(256) k_reduce(const float* __restrict__ fut) {
    __shared__ float sred[256];
    const int node  = blockIdx.x >> 3;
    const int chunk = blockIdx.x & 7;
    const int chunk_elems = NODE_ELEMS / 8;          // 36864
    const float4* p = (const float4*)(fut + (size_t)node * NODE_ELEMS +
                                      (size_t)chunk * chunk_elems);
    const int n4 = chunk_elems / 4;                  // 9216
    float lsum = 0.0f;
    for (int i = threadIdx.x; i < n4; i += 256) {
        float4 v = p[i];
        lsum += sigmoidf_(v.x) + sigmoidf_(v.y) + sigmoidf_(v.z) + sigmoidf_(v.w);
    }
    sred[threadIdx.x] = lsum;
    __syncthreads();
#pragma unroll
    for (int st = 128; st > 0; st >>= 1) {
        if (threadIdx.x < st) sred[threadIdx.x] += sred[threadIdx.x + st];
        __syncthreads();
    }
    if (threadIdx.x == 0) g_part[blockIdx.x] = sred[0];
}

// ---------------- kernel 5: plasticity epilogue -------------------------------
__global__ void k_final(const float* __restrict__ plast, const int* __restrict__ dst,
                        float* __restrict__ out_p) {
    __shared__ float smean[NN];
    int tid = threadIdx.x;
    if (tid < NN) {
        float ssum = 0.0f;
        for (int c = 0; c < 8; c++) ssum += g_part[tid * 8 + c];
        smean[tid] = ssum * (1.0f / (float)NODE_ELEMS);
    }
    __syncthreads();
    if (tid < EE)
        out_p[tid] = plast[tid] + INIT_PLAST * (smean[dst[tid]] - 0.5f);
}

// ---------------- launch ------------------------------------------------------
extern "C" void kernel_launch(void* const* d_in, const int* in_sizes, int n_in,
                              void* d_out, int out_size) {
    const float* states  = (const float*)d_in[0];
    const float* weights = (const float*)d_in[1];
    const float* plast   = (const float*)d_in[2];
    const int*   src     = (const int*)d_in[3];
    const int*   dst     = (const int*)d_in[4];
    float* out = (float*)d_out;

    k_sigmoid<<<(ACT_ELEMS / 4 + 255) / 256, 256>>>(states);
    k_meta<<<1, 128>>>(src, dst, plast);
    dim3 gconv(9, BB, NN);                 // 9 spatial tiles x 4 batch x 24 nodes
    k_conv<<<gconv, 256>>>(weights, out);
    k_reduce<<<NN * 8, 256>>>(out);
    k_final<<<1, 128>>>(plast, dst, out + FUT_ELEMS);
}

// round 5
// speedup vs baseline: 1.3352x; 1.3352x over previous
#include <cuda_runtime.h>
#include <cstdint>

// ---------------- problem constants ----------------
#define NN   24          // real nodes
#define NP1  25          // + virtual node
#define BB   4
#define CC   8
#define HH   96
#define WW   96
#define KK   4
#define EE   96
#define HW          (HH*WW)            // 9216
#define NODE_ELEMS  (BB*CC*HW)         // 294912
#define ACT_ELEMS   (NP1*NODE_ELEMS)   // 7372800
#define FUT_ELEMS   (NN*NODE_ELEMS)    // 7077888
#define INIT_PLAST  0.1f
#define NBLK        (9*BB*NN)          // 864 conv blocks

// ---------------- device scratch (no allocs allowed) ----------------
__device__ float g_act[ACT_ELEMS];        // sigmoid(states), ~29.5 MB
__device__ int   g_off[NN + 1];           // CSR offsets by dst node
__device__ int   g_edge_id[EE];           // edge index (for weights)
__device__ int   g_edge_src[EE];          // src node of edge
__device__ float g_edge_scale[EE];        // plasticity[e] / deg[dst[e]]
__device__ float g_part[NBLK];            // per-conv-block partials of sigmoid(future)

__device__ __forceinline__ float sigmoidf_(float x) {
    return 1.0f / (1.0f + __expf(-x));
}

// ---- packed f32x2 helpers (Blackwell FFMA2; PTX ISA 8.6, sm_100+) ----
__device__ __forceinline__ unsigned long long pack2_dup(float v) {
    unsigned long long r;
    asm("mov.b64 %0, {%1, %1};" : "=l"(r) : "f"(v));
    return r;
}
__device__ __forceinline__ void fma2(unsigned long long& d,
                                     unsigned long long a, unsigned long long b) {
    asm("fma.rn.f32x2 %0, %1, %2, %0;" : "+l"(d) : "l"(a), "l"(b));
}
__device__ __forceinline__ void unpack2(unsigned long long v, float& lo, float& hi) {
    asm("mov.b64 {%0, %1}, %2;" : "=f"(lo), "=f"(hi) : "l"(v));
}

// ---------------- kernel 1: act = sigmoid(states) ----------------
__global__ void k_sigmoid(const float* __restrict__ st) {
    int n4 = ACT_ELEMS / 4;
    const float4* s4 = (const float4*)st;
    float4* a4 = (float4*)g_act;
    for (int i = blockIdx.x * blockDim.x + threadIdx.x; i < n4;
         i += gridDim.x * blockDim.x) {
        float4 v = s4[i];
        v.x = sigmoidf_(v.x);
        v.y = sigmoidf_(v.y);
        v.z = sigmoidf_(v.z);
        v.w = sigmoidf_(v.w);
        a4[i] = v;
    }
}

// ---------------- kernel 2: build dst-CSR + fused scale (deterministic) --------
__global__ void k_meta(const int* __restrict__ src, const int* __restrict__ dst,
                       const float* __restrict__ plast) {
    __shared__ int ssrc[EE];
    __shared__ int sdst[EE];
    __shared__ float spl[EE];
    int tid = threadIdx.x;
    if (tid < EE) {
        ssrc[tid] = src[tid];
        sdst[tid] = dst[tid];
        spl[tid]  = plast[tid];
    }
    __syncthreads();
    if (tid == 0) {
        int cnt[NN];
        for (int n = 0; n < NN; n++) cnt[n] = 0;
        for (int e = 0; e < EE; e++) cnt[sdst[e]]++;
        int off = 0;
        int cur[NN];
        float inv[NN];
        for (int n = 0; n < NN; n++) {
            g_off[n] = off;
            cur[n] = off;
            int c = cnt[n] > 0 ? cnt[n] : 1;
            inv[n] = 1.0f / (float)c;
            off += cnt[n];
        }
        g_off[NN] = off;
        for (int e = 0; e < EE; e++) {          // stable order -> deterministic
            int d = sdst[e];
            int slot = cur[d]++;
            g_edge_id[slot]    = e;
            g_edge_src[slot]   = ssrc[e];
            g_edge_scale[slot] = spl[e] * inv[d];
        }
    }
}

// ---------------- kernel 3: conv + aggregate + fused sigmoid-sum --------------
// Tile: 32x32 output pixels per (node,b,tile). 256 threads: 32 rows x 8 thr,
// each thread computes 4 x-pixels for 8 Cout. Cout is PAIRED into f32x2 lanes:
// acc2[j][p] holds (co=2j, co=2j+1) for pixel p. Weights stored co-contiguous
// in shared so each (tap, co-pair) is one aligned LDS.64 (warp-broadcast).
__global__ void __launch_bounds__(256) k_conv(const float* __restrict__ weights,
                                              float* __restrict__ out) {
    __shared__ __align__(16) float sin_[35 * 36];  // 35x35 halo tile, stride 36
    __shared__ __align__(16) float ws2[16 * 8];    // [tap=ky*4+kx][co] * scale
    __shared__ float sred[256];

    const int node = blockIdx.z;
    const int b    = blockIdx.y;
    const int ty0  = (blockIdx.x / 3) * 32;
    const int tx0  = (blockIdx.x % 3) * 32;
    const int tid  = threadIdx.x;
    const int ty   = tid >> 3;
    const int txq  = (tid & 7) << 2;

    // precompute halo-tile load addresses once
    int lof[5], gof[5];
#pragma unroll
    for (int j = 0; j < 5; j++) {
        int i = tid + j * 256;
        lof[j] = -1;
        gof[j] = -1;
        if (i < 35 * 35) {
            int r = i / 35, c = i - r * 35;
            lof[j] = r * 36 + c;
            int gy = ty0 - 1 + r, gx = tx0 - 1 + c;
            if ((unsigned)gy < (unsigned)HH && (unsigned)gx < (unsigned)WW)
                gof[j] = gy * WW + gx;
        }
    }
    // tid<128 loads one weight scalar: co = tid>>4, tap = tid&15
    const int w_co  = tid >> 4;
    const int w_tap = tid & 15;
    const int w_dst = w_tap * 8 + w_co;                 // ws2[tap][co]
    const int w_src = w_co * (CC * KK * KK) + w_tap;    // + ci*16

    unsigned long long acc2[4][4];                      // [co-pair][pixel]
#pragma unroll
    for (int j = 0; j < 4; j++)
#pragma unroll
        for (int p = 0; p < 4; p++) acc2[j][p] = 0ULL;

    const int s0 = __ldg(&g_off[node]), s1 = __ldg(&g_off[node + 1]);
    for (int s = s0; s < s1; ++s) {
        const int   e  = __ldg(&g_edge_id[s]);
        const int   sn = __ldg(&g_edge_src[s]);
        const float sc = __ldg(&g_edge_scale[s]);
        const float* abase = g_act + ((size_t)(sn * BB + b)) * (CC * HW);
        const float* wbase = weights + (size_t)e * (CC * CC * KK * KK);

#pragma unroll 1
        for (int ci = 0; ci < CC; ci++) {
            __syncthreads();
            const float* a = abase + ci * HW;
#pragma unroll
            for (int j = 0; j < 5; j++) {
                if (lof[j] >= 0)
                    sin_[lof[j]] = (gof[j] >= 0) ? __ldg(&a[gof[j]]) : 0.0f;
            }
            if (tid < 128)
                ws2[w_dst] = __ldg(&wbase[w_src + ci * (KK * KK)]) * sc;
            __syncthreads();

#pragma unroll
            for (int ky = 0; ky < 4; ky++) {
                const float* rp = &sin_[(ty + ky) * 36 + txq];
                float4 va = *(const float4*)rp;
                float4 vb = *(const float4*)(rp + 4);
                // named registers (no local array -> no spill risk)
                const unsigned long long d0 = pack2_dup(va.x);
                const unsigned long long d1 = pack2_dup(va.y);
                const unsigned long long d2 = pack2_dup(va.z);
                const unsigned long long d3 = pack2_dup(va.w);
                const unsigned long long d4 = pack2_dup(vb.x);
                const unsigned long long d5 = pack2_dup(vb.y);
                const unsigned long long d6 = pack2_dup(vb.z);
                const unsigned long long* wrow =
                    (const unsigned long long*)&ws2[ky * 4 * 8];
#pragma unroll
                for (int j = 0; j < 4; j++) {
                    unsigned long long wp0 = wrow[0 * 4 + j];  // LDS.64 bcast
                    fma2(acc2[j][0], d0, wp0);
                    fma2(acc2[j][1], d1, wp0);
                    fma2(acc2[j][2], d2, wp0);
                    fma2(acc2[j][3], d3, wp0);
                    unsigned long long wp1 = wrow[1 * 4 + j];
                    fma2(acc2[j][0], d1, wp1);
                    fma2(acc2[j][1], d2, wp1);
                    fma2(acc2[j][2], d3, wp1);
                    fma2(acc2[j][3], d4, wp1);
                    unsigned long long wp2 = wrow[2 * 4 + j];
                    fma2(acc2[j][0], d2, wp2);
                    fma2(acc2[j][1], d3, wp2);
                    fma2(acc2[j][2], d4, wp2);
                    fma2(acc2[j][3], d5, wp2);
                    unsigned long long wp3 = wrow[3 * 4 + j];
                    fma2(acc2[j][0], d3, wp3);
                    fma2(acc2[j][1], d4, wp3);
                    fma2(acc2[j][2], d5, wp3);
                    fma2(acc2[j][3], d6, wp3);
                }
            }
        }
    }

    // epilogue: store future + accumulate sigmoid locally (deterministic order)
    const int y = ty0 + ty, x = tx0 + txq;
    float* ob = out + ((size_t)(node * BB + b)) * (CC * HW) + y * WW + x;
    float lsum = 0.0f;
#pragma unroll
    for (int j = 0; j < 4; j++) {
        float lo[4], hi[4];
#pragma unroll
        for (int p = 0; p < 4; p++) unpack2(acc2[j][p], lo[p], hi[p]);
        *(float4*)(ob + (2 * j) * HW)     = make_float4(lo[0], lo[1], lo[2], lo[3]);
        *(float4*)(ob + (2 * j + 1) * HW) = make_float4(hi[0], hi[1], hi[2], hi[3]);
#pragma unroll
        for (int p = 0; p < 4; p++)
            lsum += sigmoidf_(lo[p]) + sigmoidf_(hi[p]);
    }
    sred[tid] = lsum;
    __syncthreads();
#pragma unroll
    for (int st = 128; st > 0; st >>= 1) {
        if (tid < st) sred[tid] += sred[tid + st];
        __syncthreads();
    }
    if (tid == 0)
        g_part[node * 36 + b * 9 + blockIdx.x] = sred[0];
}

// ---------------- kernel 4: plasticity epilogue -------------------------------
__global__ void k_final(const float* __restrict__ plast, const int* __restrict__ dst,
                        float* __restrict__ out_p) {
    __shared__ float smean[NN];
    int tid = threadIdx.x;
    if (tid < NN) {
        float ssum = 0.0f;
        for (int c = 0; c < 36; c++) ssum += g_part[tid * 36 + c];
        smean[tid] = ssum * (1.0f / (float)NODE_ELEMS);
    }
    __syncthreads();
    if (tid < EE)
        out_p[tid] = plast[tid] + INIT_PLAST * (smean[dst[tid]] - 0.5f);
}

// ---------------- launch ------------------------------------------------------
extern "C" void kernel_launch(void* const* d_in, const int* in_sizes, int n_in,
                              void* d_out, int out_size) {
    const float* states  = (const float*)d_in[0];
    const float* weights = (const float*)d_in[1];
    const float* plast   = (const float*)d_in[2];
    const int*   src     = (const int*)d_in[3];
    const int*   dst     = (const int*)d_in[4];
    float* out = (float*)d_out;

    k_sigmoid<<<(ACT_ELEMS / 4 + 255) / 256, 256>>>(states);
    k_meta<<<1, 128>>>(src, dst, plast);
    dim3 gconv(9, BB, NN);                 // 9 spatial tiles x 4 batch x 24 nodes
    k_conv<<<gconv, 256>>>(weights, out);
    k_final<<<1, 128>>>(plast, dst, out + FUT_ELEMS);
}